// round 17
// baseline (speedup 1.0000x reference)
#include <cuda_runtime.h>
#include <cstdint>

#define HIDDEN  4096
#define RANK    16
#define ROWS    4
#define THREADS 256
#define NWARP   8
#define TOTAL_ROWS 16384
#define TWO_OVER_PI 0.63661977236758134f

// Dequantized weights in device scratch (no allocations).
// g_Aft[r*HIDDEN+k] = A[k][r] * sA[r] * 2/pi   (transposed, coalesced loads)
// g_Bf [r*HIDDEN+c] = B[r][c] * sB[c]
__device__ float g_Aft[RANK * HIDDEN];
__device__ float g_Bf[RANK * HIDDEN];

// --- storage-format probe (validated R4+) ---
__device__ __forceinline__ int detect_mode(const void* p) {
    const unsigned* w = (const unsigned*)p;
    int vi = 0, vf = 0;
    #pragma unroll
    for (int i = 0; i < 32; i++) {
        unsigned u = w[i];
        int s = (int)u;
        if (s >= -127 && s <= 127) vi++;
        unsigned exp = (u >> 23) & 0xffu;
        if ((u & 0x7fffffffu) == 0u || (exp >= 127u && exp <= 133u)) vf++;
    }
    if (vi >= 24) return 1;
    if (vf >= 24) return 0;
    return 2;
}
__device__ __forceinline__ float load_elem(const void* p, int mode, int i) {
    if (mode == 1) return (float)((const int*)p)[i];
    if (mode == 0) return ((const float*)p)[i];
    return (float)((const signed char*)p)[i];
}

__global__ void prep_kernel(const void* __restrict__ A, const void* __restrict__ B,
                            const float* __restrict__ sA, const float* __restrict__ sB)
{
    __shared__ int mA, mB;
    if (threadIdx.x == 0) { mA = detect_mode(A); mB = detect_mode(B); }
    __syncthreads();
    const int i = blockIdx.x * blockDim.x + threadIdx.x;    // 65536 threads
    {
        const int k = i >> 4, r = i & 15;
        g_Aft[(size_t)r * HIDDEN + k] = load_elem(A, mA, i) * sA[r] * TWO_OVER_PI;
    }
    g_Bf[i] = load_elem(B, mB, i) * sB[i & (HIDDEN - 1)];
}

// sin(t), CVT-free: magic-number rint gives q (as float, exactly) and its
// parity (mantissa bit 0); exact identity sin(t) = sin((-1)^q (t - q*pi));
// Cody-Waite 2-term pi; MUFU sin on |r| <= pi/2 (HW-accurate there).
__device__ __forceinline__ float fast_sin(float t) {
    const float MAGIC = 12582912.0f;                 // 1.5 * 2^23
    float m  = fmaf(t, 0.3183098861837907f, MAGIC);  // q in low mantissa bits
    float qf = m - MAGIC;                            // q as float (exact)
    float r  = fmaf(qf, -3.14159274101257f, t);
    r = fmaf(qf, 8.742277657e-8f, r);                // r = t - q*pi
    r = __uint_as_float(__float_as_uint(r) ^ (__float_as_uint(m) << 31));
    return __sinf(r);                                // MUFU.SIN
}

__global__ __launch_bounds__(THREADS, 2)          // 2 CTAs/SM
void pilora_kernel(const float* __restrict__ x, float* __restrict__ y)
{
    extern __shared__ float xs[];                 // [ROWS][HIDDEN]  64 KB
    __shared__ float red[NWARP][ROWS * RANK];
    __shared__ float hs[ROWS * RANK];

    const int tid  = threadIdx.x;
    const int lane = tid & 31;
    const int w    = tid >> 5;
    const size_t rowbase = (size_t)blockIdx.x * ROWS;

    // ---- phase 1: fused staging + MLP-4 weight loads + x prefetch pipeline ----
    float cur[ROWS * RANK];
    #pragma unroll
    for (int v = 0; v < ROWS * RANK; v++) cur[v] = 0.0f;

    // prefetch x for i=0 (streaming: read-once from GMEM)
    float4 xv[ROWS];
    {
        const int k0 = w * 512 + lane * 4;
        #pragma unroll
        for (int rr = 0; rr < ROWS; rr++)
            xv[rr] = __ldcs((const float4*)(x + (rowbase + rr) * HIDDEN + k0));
    }

    #pragma unroll
    for (int i = 0; i < 4; i++) {
        const int k0 = w * 512 + i * 128 + lane * 4;

        // stash current x stripe for phase 2 (warp-private)
        #pragma unroll
        for (int rr = 0; rr < ROWS; rr++)
            *(float4*)(xs + rr * HIDDEN + k0) = xv[rr];

        // prefetch next iteration's x while this iteration's FMAs run
        float4 xnext[ROWS];
        if (i < 3) {
            const int kn = k0 + 128;
            #pragma unroll
            for (int rr = 0; rr < ROWS; rr++)
                xnext[rr] = __ldcs((const float4*)(x + (rowbase + rr) * HIDDEN + kn));
        }

        #pragma unroll
        for (int rc = 0; rc < 4; rc++) {
            float4 av[4];
            #pragma unroll
            for (int c = 0; c < 4; c++)
                av[c] = *(const float4*)(g_Aft + (size_t)(rc * 4 + c) * HIDDEN + k0);
            #pragma unroll
            for (int c = 0; c < 4; c++) {
                const int r = rc * 4 + c;
                #pragma unroll
                for (int rr = 0; rr < ROWS; rr++) {
                    float t = cur[rr * RANK + r];
                    t = fmaf(xv[rr].x, av[c].x, t);
                    t = fmaf(xv[rr].y, av[c].y, t);
                    t = fmaf(xv[rr].z, av[c].z, t);
                    t = fmaf(xv[rr].w, av[c].w, t);
                    cur[rr * RANK + r] = t;
                }
            }
        }

        if (i < 3) {
            #pragma unroll
            for (int rr = 0; rr < ROWS; rr++) xv[rr] = xnext[rr];
        }
    }

    // ---- reduce-scatter butterfly: live set 64->32->16->8->4->2 (R16 win) ----
    #pragma unroll
    for (int s = 0; s < 5; s++) {
        const int E    = 64 >> s;
        const int half = E >> 1;
        const int off  = 16 >> s;
        const bool bit = (lane & off) != 0;
        #pragma unroll
        for (int j = 0; j < half; j++) {
            const float a = cur[j];
            const float b = cur[half + j];
            const float send = bit ? a : b;
            const float recv = __shfl_xor_sync(0xffffffffu, send, off);
            const float keep = bit ? b : a;
            cur[j] = keep + recv;
        }
    }
    red[w][2 * lane]     = cur[0];
    red[w][2 * lane + 1] = cur[1];

    // Pre-barrier prefetch: first B chunk (i=0, rc=0) is hs-independent.
    float4 bpre[4];
    {
        const int c0 = w * 512 + lane * 4;
        #pragma unroll
        for (int c = 0; c < 4; c++)
            bpre[c] = *(const float4*)(g_Bf + (size_t)c * HIDDEN + c0);
    }
    __syncthreads();

    if (tid < ROWS * RANK) {
        float h = 0.0f;
        #pragma unroll
        for (int ww = 0; ww < NWARP; ww++) h += red[ww][tid];
        hs[tid] = h;                       // sA and 2/pi already folded into Aft
    }
    __syncthreads();

    // ---- phase 2: y = x + 2*sin( sum_r hs[row][r] * Bf[r][c] ), B pipelined ----
    #pragma unroll
    for (int i = 0; i < 4; i++) {
        const int c0 = w * 512 + i * 128 + lane * 4;

        float acc2[ROWS][4];
        #pragma unroll
        for (int rr = 0; rr < ROWS; rr++)
            #pragma unroll
            for (int j = 0; j < 4; j++)
                acc2[rr][j] = 0.0f;

        float4 bv[4];
        if (i == 0) {
            #pragma unroll
            for (int c = 0; c < 4; c++) bv[c] = bpre[c];
        } else {
            #pragma unroll
            for (int c = 0; c < 4; c++)
                bv[c] = *(const float4*)(g_Bf + (size_t)c * HIDDEN + c0);
        }

        #pragma unroll
        for (int rc = 0; rc < 4; rc++) {
            // prefetch next rank-chunk while current chunk's FMAs run
            float4 bnext[4];
            if (rc < 3) {
                #pragma unroll
                for (int c = 0; c < 4; c++)
                    bnext[c] = *(const float4*)(g_Bf +
                                 (size_t)((rc + 1) * 4 + c) * HIDDEN + c0);
            }
            #pragma unroll
            for (int c = 0; c < 4; c++) {
                const int r = rc * 4 + c;
                #pragma unroll
                for (int rr = 0; rr < ROWS; rr++) {
                    const float hr = hs[rr * RANK + r];   // conflict-free broadcast
                    acc2[rr][0] = fmaf(hr, bv[c].x, acc2[rr][0]);
                    acc2[rr][1] = fmaf(hr, bv[c].y, acc2[rr][1]);
                    acc2[rr][2] = fmaf(hr, bv[c].z, acc2[rr][2]);
                    acc2[rr][3] = fmaf(hr, bv[c].w, acc2[rr][3]);
                }
            }
            if (rc < 3) {
                #pragma unroll
                for (int c = 0; c < 4; c++) bv[c] = bnext[c];
            }
        }

        #pragma unroll
        for (int rr = 0; rr < ROWS; rr++) {
            const float4 xv2 = *(const float4*)(xs + rr * HIDDEN + c0);
            float4 ov;
            ov.x = fmaf(2.0f, fast_sin(acc2[rr][0]), xv2.x);
            ov.y = fmaf(2.0f, fast_sin(acc2[rr][1]), xv2.y);
            ov.z = fmaf(2.0f, fast_sin(acc2[rr][2]), xv2.z);
            ov.w = fmaf(2.0f, fast_sin(acc2[rr][3]), xv2.w);
            *(float4*)(y + (rowbase + rr) * HIDDEN + c0) = ov;
        }
    }
}

extern "C" void kernel_launch(void* const* d_in, const int* in_sizes, int n_in,
                              void* d_out, int out_size)
{
    // Rank-order binding by size (robust; validated since R4)
    int idx[16];
    const int m = (n_in < 16) ? n_in : 16;
    for (int i = 0; i < m; i++) idx[i] = i;
    for (int i = 0; i < m; i++) {
        int best = i;
        for (int j = i + 1; j < m; j++)
            if (in_sizes[idx[j]] < in_sizes[idx[best]]) best = j;
        if (best != i) {
            int t = idx[best];
            for (int j = best; j > i; j--) idx[j] = idx[j - 1];
            idx[i] = t;
        }
    }
    const float* sA = (const float*)d_in[idx[0]];
    const float* sB = (const float*)d_in[idx[1]];
    const void*  A  = d_in[idx[2]];
    const void*  B  = d_in[idx[3]];
    const float* x  = (const float*)d_in[idx[m - 1]];
    float* y = (float*)d_out;

    prep_kernel<<<(HIDDEN * RANK) / 256, 256>>>(A, B, sA, sB);

    const size_t smem = (size_t)ROWS * HIDDEN * sizeof(float);   // 64 KB
    cudaFuncSetAttribute(pilora_kernel,
                         cudaFuncAttributeMaxDynamicSharedMemorySize, (int)smem);
    pilora_kernel<<<TOTAL_ROWS / ROWS, THREADS, smem>>>(x, y);
}